// round 1
// baseline (speedup 1.0000x reference)
#include <cuda_runtime.h>

// ---------------- model constants ----------------
#define NL     2
#define D      768
#define DI     1536
#define NSTATE 16
#define DR     48
#define KCONV  4
#define VOC    32000
#define BB     2
#define LSEQ   1024
#define TOK    (BB*LSEQ)        // 2048
#define BCDW   (2*NSTATE+DR)    // 80
#define EPS    1e-5f

// ---------------- scratch (device globals; no allocation allowed) ----------
__device__ float g_h [TOK*D];
__device__ float g_hn[TOK*D];
__device__ float g_xz[TOK*2*DI];
__device__ float g_xi[TOK*DI];
__device__ float g_bcd[TOK*BCDW];
__device__ float g_delta[TOK*DI];
__device__ float g_y [TOK*DI];

// ---------------- packed f32x2 helpers (Blackwell) ----------------
__device__ __forceinline__ unsigned long long pk2(float x) {
    unsigned long long r; unsigned int xi = __float_as_uint(x);
    asm("mov.b64 %0, {%1, %1};" : "=l"(r) : "r"(xi));
    return r;
}
__device__ __forceinline__ void ffma2(unsigned long long& d,
                                      unsigned long long a,
                                      unsigned long long b) {
    asm("fma.rn.f32x2 %0, %1, %2, %0;" : "+l"(d) : "l"(a), "l"(b));
}

// ---------------- embedding gather ----------------
__global__ void embed_k(const int* __restrict__ x, const float* __restrict__ emb,
                        float* __restrict__ h) {
    int t = blockIdx.x;                       // 0..TOK-1
    int v = x[t];
    const float4* src = (const float4*)(emb + (size_t)v * D);
    float4* dst = (float4*)(h + (size_t)t * D);
    for (int i = threadIdx.x; i < D / 4; i += blockDim.x) dst[i] = src[i];
}

// ---------------- rmsnorm (block per token row) ----------------
__global__ void rmsnorm_k(const float* __restrict__ in, const float* __restrict__ w,
                          float* __restrict__ out) {
    int t = blockIdx.x;
    const float* row = in + (size_t)t * D;
    float s = 0.f;
    for (int i = threadIdx.x; i < D; i += blockDim.x) { float v = row[i]; s += v * v; }
    __shared__ float red[8];
    #pragma unroll
    for (int o = 16; o; o >>= 1) s += __shfl_xor_sync(0xffffffffu, s, o);
    if ((threadIdx.x & 31) == 0) red[threadIdx.x >> 5] = s;
    __syncthreads();
    if (threadIdx.x < 8) {
        float v = red[threadIdx.x];
        #pragma unroll
        for (int o = 4; o; o >>= 1) v += __shfl_xor_sync(0xffu, v, o);
        if (threadIdx.x == 0) red[0] = v;
    }
    __syncthreads();
    float inv = rsqrtf(red[0] / (float)D + EPS);
    for (int i = threadIdx.x; i < D; i += blockDim.x)
        out[(size_t)t * D + i] = row[i] * inv * w[i];
}

// ---------------- depthwise causal conv + silu ----------------
__global__ void conv_silu_k(const float* __restrict__ xz, const float* __restrict__ cw,
                            const float* __restrict__ cb, float* __restrict__ xi) {
    int idx = blockIdx.x * blockDim.x + threadIdx.x;   // over TOK*DI
    if (idx >= TOK * DI) return;
    int d = idx % DI; int t = idx / DI; int l = t % LSEQ; int tb = t - l;
    float acc = cb[d];
    #pragma unroll
    for (int k = 0; k < KCONV; k++) {
        int ls = l + k - (KCONV - 1);
        if (ls >= 0) acc += xz[(size_t)(tb + ls) * (2 * DI) + d] * cw[d * KCONV + k];
    }
    xi[idx] = acc / (1.f + expf(-acc));
}

// ---------------- delta = softplus(z + db) ----------------
__global__ void softplus_k(float* __restrict__ delta, const float* __restrict__ db) {
    int idx = blockIdx.x * blockDim.x + threadIdx.x;
    if (idx >= TOK * DI) return;
    int d = idx % DI;
    float z = delta[idx] + db[d];
    delta[idx] = (z > 20.f) ? z : log1pf(expf(z));
}

// ---------------- gate: y *= silu(res) ----------------
__global__ void gate_k(float* __restrict__ y, const float* __restrict__ xz) {
    int idx = blockIdx.x * blockDim.x + threadIdx.x;
    if (idx >= TOK * DI) return;
    int d = idx % DI; int t = idx / DI;
    float r = xz[(size_t)t * (2 * DI) + DI + d];
    y[idx] *= r / (1.f + expf(-r));
}

// ---------------- selective scan: thread = (b, d, n) ----------------
__global__ void scan_k(const float* __restrict__ lA, const float* __restrict__ Dp,
                       const float* __restrict__ bcd, const float* __restrict__ delta,
                       const float* __restrict__ xi, float* __restrict__ y) {
    int ch = threadIdx.x >> 4;                // 0..7  channel within block
    int n  = threadIdx.x & 15;
    int b  = blockIdx.x / (DI / 8);
    int d  = (blockIdx.x % (DI / 8)) * 8 + ch;
    float Av = -expf(lA[d * NSTATE + n]);
    float Dv = Dp[d];
    float hs = 0.f;
    const float* bcd_p = bcd   + (size_t)b * LSEQ * BCDW;
    const float* del_p = delta + (size_t)b * LSEQ * DI + d;
    const float* xi_p  = xi    + (size_t)b * LSEQ * DI + d;
    float*       y_p   = y     + (size_t)b * LSEQ * DI + d;
    for (int l = 0; l < LSEQ; l++) {
        float dl = del_p[(size_t)l * DI];
        float Bn = bcd_p[l * BCDW + n];
        float Cn = bcd_p[l * BCDW + NSTATE + n];
        float xv = xi_p[(size_t)l * DI];
        float dA = dl * Av;
        float em = expm1f(dA);
        float Abar = em + 1.f;
        float r = (dA != 0.f) ? (em / dA) : 1.f;
        hs = Abar * hs + r * dl * Bn * xv;
        float c = Cn * hs;
        c += __shfl_xor_sync(0xffffffffu, c, 1);
        c += __shfl_xor_sync(0xffffffffu, c, 2);
        c += __shfl_xor_sync(0xffffffffu, c, 4);
        c += __shfl_xor_sync(0xffffffffu, c, 8);
        if (n == 0) y_p[(size_t)l * DI] = c + xv * Dv;
    }
}

// ---------------- NT SGEMM: C[M,N] (+)= A[M,K] * B[N,K]^T  (f32x2 packed) ----
#define BM 128
#define BN 128
#define BKg 8
__global__ __launch_bounds__(256) void gemm_nt(
    const float* __restrict__ A, const float* __restrict__ Bw, float* __restrict__ C,
    int M, int Nn, int K, int lda, int ldb, int ldc, int accum) {
    __shared__ float As[BKg][BM + 4];
    __shared__ float Bs[BKg][BN + 4];
    int tid = threadIdx.x;
    int tx = tid & 15, ty = tid >> 4;
    int bm = blockIdx.y * BM, bn = blockIdx.x * BN;

    int lr = tid >> 1;            // 0..127
    int lk = (tid & 1) * 4;       // 0 or 4
    const float* Ap = A + (size_t)(bm + lr) * lda + lk;
    int brow = bn + lr;
    const float* Bp = Bw + (size_t)brow * ldb + lk;
    bool bok = brow < Nn;

    unsigned long long acc[32];
    #pragma unroll
    for (int i = 0; i < 32; i++) acc[i] = 0ull;

    int nIt = K / BKg;
    float4 aReg = *(const float4*)Ap;
    float4 bReg = bok ? *(const float4*)Bp : make_float4(0.f, 0.f, 0.f, 0.f);

    for (int it = 0; it < nIt; ++it) {
        As[lk + 0][lr] = aReg.x; As[lk + 1][lr] = aReg.y;
        As[lk + 2][lr] = aReg.z; As[lk + 3][lr] = aReg.w;
        Bs[lk + 0][lr] = bReg.x; Bs[lk + 1][lr] = bReg.y;
        Bs[lk + 2][lr] = bReg.z; Bs[lk + 3][lr] = bReg.w;
        __syncthreads();
        if (it + 1 < nIt) {
            aReg = *(const float4*)(Ap + (size_t)(it + 1) * BKg);
            bReg = bok ? *(const float4*)(Bp + (size_t)(it + 1) * BKg)
                       : make_float4(0.f, 0.f, 0.f, 0.f);
        }
        #pragma unroll
        for (int k = 0; k < BKg; k++) {
            float4 a0 = *(const float4*)&As[k][ty * 4];
            float4 a1 = *(const float4*)&As[k][64 + ty * 4];
            ulonglong2 b0 = *(const ulonglong2*)&Bs[k][tx * 4];
            ulonglong2 b1 = *(const ulonglong2*)&Bs[k][64 + tx * 4];
            unsigned long long ap[8];
            ap[0] = pk2(a0.x); ap[1] = pk2(a0.y); ap[2] = pk2(a0.z); ap[3] = pk2(a0.w);
            ap[4] = pk2(a1.x); ap[5] = pk2(a1.y); ap[6] = pk2(a1.z); ap[7] = pk2(a1.w);
            #pragma unroll
            for (int i = 0; i < 8; i++) {
                ffma2(acc[i * 4 + 0], ap[i], b0.x);
                ffma2(acc[i * 4 + 1], ap[i], b0.y);
                ffma2(acc[i * 4 + 2], ap[i], b1.x);
                ffma2(acc[i * 4 + 3], ap[i], b1.y);
            }
        }
        __syncthreads();
    }

    #pragma unroll
    for (int gi = 0; gi < 2; gi++)
    #pragma unroll
    for (int i = 0; i < 4; i++) {
        int row = bm + gi * 64 + ty * 4 + i;
        float* crow = C + (size_t)row * ldc + bn;
        #pragma unroll
        for (int gj = 0; gj < 2; gj++)
        #pragma unroll
        for (int jp = 0; jp < 2; jp++) {
            int col = gj * 64 + tx * 4 + jp * 2;
            unsigned long long v = acc[(gi * 4 + i) * 4 + gj * 2 + jp];
            float lo = __uint_as_float((unsigned)(v & 0xffffffffull));
            float hi = __uint_as_float((unsigned)(v >> 32));
            if (bn + col < Nn)     { if (accum) crow[col]     += lo; else crow[col]     = lo; }
            if (bn + col + 1 < Nn) { if (accum) crow[col + 1] += hi; else crow[col + 1] = hi; }
        }
    }
}

// ---------------- residual add is fused via accum=1 on out_proj GEMM --------

extern "C" void kernel_launch(void* const* d_in, const int* in_sizes, int n_in,
                              void* d_out, int out_size) {
    const int*   x        = (const int*)  d_in[0];
    const float* emb      = (const float*)d_in[1];
    const float* rms_w    = (const float*)d_in[2];
    const float* in_w     = (const float*)d_in[3];
    const float* conv_w   = (const float*)d_in[4];
    const float* conv_b   = (const float*)d_in[5];
    const float* lA       = (const float*)d_in[6];
    const float* bcw      = (const float*)d_in[7];
    const float* dup_w    = (const float*)d_in[8];
    const float* dup_b    = (const float*)d_in[9];
    const float* D_param  = (const float*)d_in[10];
    const float* out_w    = (const float*)d_in[11];
    const float* norm_f_w = (const float*)d_in[12];
    float* out = (float*)d_out;

    float *h, *hn, *xz, *xi, *bcd, *delta, *y;
    cudaGetSymbolAddress((void**)&h,    g_h);
    cudaGetSymbolAddress((void**)&hn,   g_hn);
    cudaGetSymbolAddress((void**)&xz,   g_xz);
    cudaGetSymbolAddress((void**)&xi,   g_xi);
    cudaGetSymbolAddress((void**)&bcd,  g_bcd);
    cudaGetSymbolAddress((void**)&delta,g_delta);
    cudaGetSymbolAddress((void**)&y,    g_y);

    const int EW = (TOK * DI + 255) / 256;

    embed_k<<<TOK, 256>>>(x, emb, h);

    for (int l = 0; l < NL; l++) {
        const float* in_wl  = in_w  + (size_t)l * 2 * DI * D;
        const float* cwl    = conv_w + (size_t)l * DI * KCONV;
        const float* cbl    = conv_b + (size_t)l * DI;
        const float* lAl    = lA     + (size_t)l * DI * NSTATE;
        const float* bcwl   = bcw    + (size_t)l * BCDW * DI;
        const float* dwl    = dup_w  + (size_t)l * DI * DR;
        const float* dbl    = dup_b  + (size_t)l * DI;
        const float* Dpl    = D_param + (size_t)l * DI;
        const float* owl    = out_w  + (size_t)l * D * DI;

        rmsnorm_k<<<TOK, 256>>>(h, rms_w + (size_t)l * D, hn);
        gemm_nt<<<dim3(2 * DI / BN, TOK / BM), 256>>>(hn, in_wl, xz,
                TOK, 2 * DI, D, D, D, 2 * DI, 0);
        conv_silu_k<<<EW, 256>>>(xz, cwl, cbl, xi);
        gemm_nt<<<dim3(1, TOK / BM), 256>>>(xi, bcwl, bcd,
                TOK, BCDW, DI, DI, DI, BCDW, 0);
        gemm_nt<<<dim3(DI / BN, TOK / BM), 256>>>(bcd + 2 * NSTATE, dwl, delta,
                TOK, DI, DR, BCDW, DR, DI, 0);
        softplus_k<<<EW, 256>>>(delta, dbl);
        scan_k<<<BB * (DI / 8), 128>>>(lAl, Dpl, bcd, delta, xi, y);
        gate_k<<<EW, 256>>>(y, xz);
        gemm_nt<<<dim3(D / BN, TOK / BM), 256>>>(y, owl, h,
                TOK, D, DI, DI, DI, D, 1);   // accum=1: fused residual add
    }

    rmsnorm_k<<<TOK, 256>>>(h, norm_f_w, hn);
    gemm_nt<<<dim3(VOC / BN, TOK / BM), 256>>>(hn, emb, out,
            TOK, VOC, D, D, D, VOC, 0);
}

// round 3
// speedup vs baseline: 1.4080x; 1.4080x over previous
#include <cuda_runtime.h>
#include <cuda_bf16.h>
#include <cstdint>

// ---------------- model constants ----------------
#define NL     2
#define D      768
#define DI     1536
#define NSTATE 16
#define DR     48
#define KCONV  4
#define VOC    32000
#define BB     2
#define LSEQ   1024
#define TOK    (BB*LSEQ)        // 2048
#define BCDW   (2*NSTATE+DR)    // 80
#define EPS    1e-5f

// ---------------- scratch (device globals; no allocation allowed) ----------
__device__ __align__(256) float g_h [TOK*D];
__device__ __align__(256) float g_hn[TOK*D];
__device__ __align__(256) float g_xz[TOK*2*DI];
__device__ __align__(256) float g_xi[TOK*DI];
__device__ __align__(256) float g_bcd[TOK*BCDW];
__device__ __align__(256) float g_delta[TOK*DI];
__device__ __align__(256) float g_y [TOK*DI];
// bf16 split operand buffers
__device__ __align__(256) __nv_bfloat16 g_eh[VOC*D];
__device__ __align__(256) __nv_bfloat16 g_el[VOC*D];
__device__ __align__(256) __nv_bfloat16 g_wh[2*DI*D];
__device__ __align__(256) __nv_bfloat16 g_wl[2*DI*D];
__device__ __align__(256) __nv_bfloat16 g_ah[TOK*DI];
__device__ __align__(256) __nv_bfloat16 g_al[TOK*DI];

// ---------------- helpers ----------------
__device__ __forceinline__ uint32_t s2u(const void* p) {
    uint32_t a;
    asm("{ .reg .u64 t; cvta.to.shared.u64 t, %1; cvt.u32.u64 %0, t; }" : "=r"(a) : "l"(p));
    return a;
}
__device__ __forceinline__ void cp16(uint32_t saddr, const void* gaddr, int sz) {
    asm volatile("cp.async.cg.shared.global [%0], [%1], 16, %2;"
                 :: "r"(saddr), "l"(gaddr), "r"(sz) : "memory");
}
__device__ __forceinline__ void ldmx4(uint32_t* r, uint32_t addr) {
    asm volatile("ldmatrix.sync.aligned.m8n8.x4.shared.b16 {%0,%1,%2,%3}, [%4];"
                 : "=r"(r[0]), "=r"(r[1]), "=r"(r[2]), "=r"(r[3]) : "r"(addr));
}
__device__ __forceinline__ void mma16816(float* c, const uint32_t* a, const uint32_t* b) {
    asm volatile("mma.sync.aligned.m16n8k16.row.col.f32.bf16.bf16.f32 "
                 "{%0,%1,%2,%3}, {%4,%5,%6,%7}, {%8,%9}, {%0,%1,%2,%3};"
                 : "+f"(c[0]), "+f"(c[1]), "+f"(c[2]), "+f"(c[3])
                 : "r"(a[0]), "r"(a[1]), "r"(a[2]), "r"(a[3]), "r"(b[0]), "r"(b[1]));
}

// ---------------- bf16 hi/lo split convert (K padding & strided src) --------
__global__ void cvt_k(const float* __restrict__ src, __nv_bfloat16* __restrict__ hi,
                      __nv_bfloat16* __restrict__ lo, int rows, int K, int Kpad,
                      int lda, int off) {
    int idx = blockIdx.x * blockDim.x + threadIdx.x;
    if (idx >= rows * Kpad) return;
    int r = idx / Kpad, k = idx - r * Kpad;
    float v = (k < K) ? src[(size_t)r * lda + off + k] : 0.f;
    __nv_bfloat16 h = __float2bfloat16(v);
    hi[idx] = h;
    lo[idx] = __float2bfloat16(v - __bfloat162float(h));
}

// ---------------- HMMA split-bf16 NT GEMM ----------------
// C[M,N] (+)= A[M,K] * B[N,K]^T.  CTA 128x128, BK=64, 3-stage cp.async.
#define GS_STAGES 3
#define GS_BYTES  65536   // per stage: Ah 16K | Al 16K | Bh 16K | Bl 16K

__global__ void __launch_bounds__(256, 1) gemm_mma(
    const __nv_bfloat16* __restrict__ Ah, const __nv_bfloat16* __restrict__ Al,
    const __nv_bfloat16* __restrict__ Bh, const __nv_bfloat16* __restrict__ Bl,
    float* __restrict__ C, int Nn, int Kpad, int ldc, int accum) {
    extern __shared__ __align__(1024) char gsm[];
    const uint32_t sb = s2u(gsm);
    const int tid = threadIdx.x, lane = tid & 31, wid = tid >> 5;
    const int bm = blockIdx.x * 128, bn = blockIdx.y * 128;
    const int mw = wid & 1, nw = wid >> 1;     // warp tile: 64(M) x 32(N)
    const int nK = Kpad >> 6;

    // per-thread load geometry: row = tid>>3 (+q*32), chunk = tid&7
    const int lr = tid >> 3, lch = tid & 7;

    auto issue = [&](int s) {
        if (s < nK) {
            uint32_t buf = sb + (s % GS_STAGES) * GS_BYTES;
            int kb = s << 6;
            #pragma unroll
            for (int q = 0; q < 4; q++) {
                int r = lr + q * 32;
                uint32_t so = (uint32_t)(r * 128 + ((lch ^ (r & 7)) << 4));
                size_t ga = (size_t)(bm + r) * Kpad + kb + (lch << 3);
                cp16(buf + so,         Ah + ga, 16);
                cp16(buf + 16384 + so, Al + ga, 16);
                int rb = bn + r;
                int sz = (rb < Nn) ? 16 : 0;
                size_t gb = (size_t)((rb < Nn) ? rb : 0) * Kpad + kb + (lch << 3);
                cp16(buf + 32768 + so, Bh + gb, sz);
                cp16(buf + 49152 + so, Bl + gb, sz);
            }
        }
        asm volatile("cp.async.commit_group;" ::: "memory");
    };

    float acc[4][4][4];
    #pragma unroll
    for (int i = 0; i < 4; i++)
        #pragma unroll
        for (int j = 0; j < 4; j++)
            #pragma unroll
            for (int v = 0; v < 4; v++) acc[i][j][v] = 0.f;

    // ldmatrix per-lane address components
    const int lrow8 = (lane & 7) + ((lane >> 3) & 1) * 8;   // row within 16
    const int lkh   = lane >> 4;                            // k-half (0/1)

    // prologue: stages 0..GS_STAGES-2
    #pragma unroll
    for (int s = 0; s < GS_STAGES - 1; s++) issue(s);

    for (int it = 0; it < nK; ++it) {
        asm volatile("cp.async.wait_group %0;" :: "n"(GS_STAGES - 2) : "memory");
        __syncthreads();
        uint32_t base = sb + (it % GS_STAGES) * GS_BYTES;
        #pragma unroll
        for (int kc = 0; kc < 4; kc++) {
            uint32_t ah[4][4], al[4][4], bh[4][2], bl[4][2];
            #pragma unroll
            for (int ma = 0; ma < 4; ma++) {
                int r = mw * 64 + ma * 16 + lrow8;
                int cc = kc * 2 + lkh;
                uint32_t ad = base + r * 128 + ((cc ^ (r & 7)) << 4);
                ldmx4(ah[ma], ad);
                ldmx4(al[ma], ad + 16384);
            }
            #pragma unroll
            for (int nb = 0; nb < 2; nb++) {
                int r = nw * 32 + nb * 16 + lrow8;
                int cc = kc * 2 + lkh;
                uint32_t bd = base + 32768 + r * 128 + ((cc ^ (r & 7)) << 4);
                uint32_t t[4];
                ldmx4(t, bd);
                bh[nb*2][0] = t[0]; bh[nb*2+1][0] = t[1];
                bh[nb*2][1] = t[2]; bh[nb*2+1][1] = t[3];
                ldmx4(t, bd + 16384);
                bl[nb*2][0] = t[0]; bl[nb*2+1][0] = t[1];
                bl[nb*2][1] = t[2]; bl[nb*2+1][1] = t[3];
            }
            #pragma unroll
            for (int ma = 0; ma < 4; ma++)
                #pragma unroll
                for (int na = 0; na < 4; na++) {
                    mma16816(acc[ma][na], ah[ma], bh[na]);
                    mma16816(acc[ma][na], ah[ma], bl[na]);
                    mma16816(acc[ma][na], al[ma], bh[na]);
                }
        }
        __syncthreads();
        issue(it + GS_STAGES - 1);
    }

    // epilogue
    #pragma unroll
    for (int ma = 0; ma < 4; ma++) {
        int row0 = bm + mw * 64 + ma * 16 + (lane >> 2);
        #pragma unroll
        for (int na = 0; na < 4; na++) {
            int col = bn + nw * 32 + na * 8 + (lane & 3) * 2;
            if (col < Nn) {
                float* p0 = C + (size_t)row0 * ldc + col;
                float* p1 = C + (size_t)(row0 + 8) * ldc + col;
                float2 v0 = make_float2(acc[ma][na][0], acc[ma][na][1]);
                float2 v1 = make_float2(acc[ma][na][2], acc[ma][na][3]);
                if (accum) {
                    float2 o0 = *(float2*)p0, o1 = *(float2*)p1;
                    v0.x += o0.x; v0.y += o0.y; v1.x += o1.x; v1.y += o1.y;
                }
                *(float2*)p0 = v0;
                *(float2*)p1 = v1;
            }
        }
    }
}

// ---------------- embedding gather ----------------
__global__ void embed_k(const int* __restrict__ x, const float* __restrict__ emb,
                        float* __restrict__ h) {
    int t = blockIdx.x;
    int v = x[t];
    const float4* src = (const float4*)(emb + (size_t)v * D);
    float4* dst = (float4*)(h + (size_t)t * D);
    for (int i = threadIdx.x; i < D / 4; i += blockDim.x) dst[i] = src[i];
}

// ---------------- rmsnorm ----------------
__global__ void rmsnorm_k(const float* __restrict__ in, const float* __restrict__ w,
                          float* __restrict__ out) {
    int t = blockIdx.x;
    const float* row = in + (size_t)t * D;
    float s = 0.f;
    for (int i = threadIdx.x; i < D; i += blockDim.x) { float v = row[i]; s += v * v; }
    __shared__ float red[8];
    #pragma unroll
    for (int o = 16; o; o >>= 1) s += __shfl_xor_sync(0xffffffffu, s, o);
    if ((threadIdx.x & 31) == 0) red[threadIdx.x >> 5] = s;
    __syncthreads();
    if (threadIdx.x < 8) {
        float v = red[threadIdx.x];
        #pragma unroll
        for (int o = 4; o; o >>= 1) v += __shfl_xor_sync(0xffu, v, o);
        if (threadIdx.x == 0) red[0] = v;
    }
    __syncthreads();
    float inv = rsqrtf(red[0] / (float)D + EPS);
    for (int i = threadIdx.x; i < D; i += blockDim.x)
        out[(size_t)t * D + i] = row[i] * inv * w[i];
}

// ---------------- depthwise causal conv + silu ----------------
__global__ void conv_silu_k(const float* __restrict__ xz, const float* __restrict__ cw,
                            const float* __restrict__ cb, float* __restrict__ xi) {
    int idx = blockIdx.x * blockDim.x + threadIdx.x;
    if (idx >= TOK * DI) return;
    int d = idx % DI; int t = idx / DI; int l = t % LSEQ; int tb = t - l;
    float acc = cb[d];
    #pragma unroll
    for (int k = 0; k < KCONV; k++) {
        int ls = l + k - (KCONV - 1);
        if (ls >= 0) acc += xz[(size_t)(tb + ls) * (2 * DI) + d] * cw[d * KCONV + k];
    }
    xi[idx] = acc / (1.f + __expf(-acc));
}

// ---------------- delta = softplus(z + db) ----------------
__global__ void softplus_k(float* __restrict__ delta, const float* __restrict__ db) {
    int idx = blockIdx.x * blockDim.x + threadIdx.x;
    if (idx >= TOK * DI) return;
    int d = idx % DI;
    float z = delta[idx] + db[d];
    delta[idx] = (z > 20.f) ? z : log1pf(expf(z));
}

// ---------------- selective scan (gate fused) ----------------
__global__ void scan_k(const float* __restrict__ lA, const float* __restrict__ Dp,
                       const float* __restrict__ bcd, const float* __restrict__ delta,
                       const float* __restrict__ xi, const float* __restrict__ xz,
                       float* __restrict__ y) {
    int ch = threadIdx.x >> 4;
    int n  = threadIdx.x & 15;
    int b  = blockIdx.x / (DI / 8);
    int d  = (blockIdx.x % (DI / 8)) * 8 + ch;
    float Av = -expf(lA[d * NSTATE + n]);
    float invA = 1.f / Av;
    float Dv = Dp[d];
    float hs = 0.f;
    const float* bp = bcd   + (size_t)b * LSEQ * BCDW;
    const float* dp = delta + (size_t)b * LSEQ * DI + d;
    const float* xp = xi    + (size_t)b * LSEQ * DI + d;
    const float* rp = xz    + (size_t)b * LSEQ * 2 * DI + DI + d;
    float*       yp = y     + (size_t)b * LSEQ * DI + d;
    #pragma unroll 2
    for (int l = 0; l < LSEQ; l++) {
        float dl = dp[(size_t)l * DI];
        float Bn = bp[l * BCDW + n];
        float Cn = bp[l * BCDW + NSTATE + n];
        float xv = xp[(size_t)l * DI];
        float dA = dl * Av;
        float em = expm1f(dA);                 // (A_bar - 1)
        float g  = invA * Bn * xv;             // em * g == B_bar * x
        hs = fmaf(em + 1.f, hs, em * g);
        float c = Cn * hs;
        c += __shfl_xor_sync(0xffffffffu, c, 1);
        c += __shfl_xor_sync(0xffffffffu, c, 2);
        c += __shfl_xor_sync(0xffffffffu, c, 4);
        c += __shfl_xor_sync(0xffffffffu, c, 8);
        if (n == 0) {
            float r = rp[(size_t)l * (2 * DI)];
            float sg = r / (1.f + __expf(-r));
            yp[(size_t)l * DI] = (c + xv * Dv) * sg;
        }
    }
}

// ---------------- launch ----------------
extern "C" void kernel_launch(void* const* d_in, const int* in_sizes, int n_in,
                              void* d_out, int out_size) {
    const int*   x        = (const int*)  d_in[0];
    const float* emb      = (const float*)d_in[1];
    const float* rms_w    = (const float*)d_in[2];
    const float* in_w     = (const float*)d_in[3];
    const float* conv_w   = (const float*)d_in[4];
    const float* conv_b   = (const float*)d_in[5];
    const float* lA       = (const float*)d_in[6];
    const float* bcw      = (const float*)d_in[7];
    const float* dup_w    = (const float*)d_in[8];
    const float* dup_b    = (const float*)d_in[9];
    const float* D_param  = (const float*)d_in[10];
    const float* out_w    = (const float*)d_in[11];
    const float* norm_f_w = (const float*)d_in[12];
    float* out = (float*)d_out;

    float *h, *hn, *xz, *xi, *bcd, *delta, *y;
    __nv_bfloat16 *eh, *el, *wh, *wl, *ah, *al;
    cudaGetSymbolAddress((void**)&h,    g_h);
    cudaGetSymbolAddress((void**)&hn,   g_hn);
    cudaGetSymbolAddress((void**)&xz,   g_xz);
    cudaGetSymbolAddress((void**)&xi,   g_xi);
    cudaGetSymbolAddress((void**)&bcd,  g_bcd);
    cudaGetSymbolAddress((void**)&delta,g_delta);
    cudaGetSymbolAddress((void**)&y,    g_y);
    cudaGetSymbolAddress((void**)&eh,   g_eh);
    cudaGetSymbolAddress((void**)&el,   g_el);
    cudaGetSymbolAddress((void**)&wh,   g_wh);
    cudaGetSymbolAddress((void**)&wl,   g_wl);
    cudaGetSymbolAddress((void**)&ah,   g_ah);
    cudaGetSymbolAddress((void**)&al,   g_al);

    const int SMB = GS_STAGES * GS_BYTES;   // 196608
    cudaFuncSetAttribute(gemm_mma, cudaFuncAttributeMaxDynamicSharedMemorySize, SMB);

    const int EW = (TOK * DI + 255) / 256;
    #define CVT(src, dh, dl, rows, K, Kpad, lda, off) \
        cvt_k<<<((rows)*(Kpad) + 255) / 256, 256>>>(src, dh, dl, rows, K, Kpad, lda, off)

    embed_k<<<TOK, 256>>>(x, emb, h);
    CVT(emb, eh, el, VOC, D, D, D, 0);        // embedding -> logits B operand

    for (int l = 0; l < NL; l++) {
        const float* in_wl = in_w   + (size_t)l * 2 * DI * D;
        const float* cwl   = conv_w + (size_t)l * DI * KCONV;
        const float* cbl   = conv_b + (size_t)l * DI;
        const float* lAl   = lA     + (size_t)l * DI * NSTATE;
        const float* bcwl  = bcw    + (size_t)l * BCDW * DI;
        const float* dwl   = dup_w  + (size_t)l * DI * DR;
        const float* dbl   = dup_b  + (size_t)l * DI;
        const float* Dpl   = D_param + (size_t)l * DI;
        const float* owl   = out_w  + (size_t)l * D * DI;

        rmsnorm_k<<<TOK, 256>>>(h, rms_w + (size_t)l * D, hn);
        CVT(hn, ah, al, TOK, D, D, D, 0);
        CVT(in_wl, wh, wl, 2 * DI, D, D, D, 0);
        gemm_mma<<<dim3(TOK / 128, (2 * DI) / 128), 256, SMB>>>(ah, al, wh, wl, xz,
                2 * DI, D, 2 * DI, 0);
        conv_silu_k<<<EW, 256>>>(xz, cwl, cbl, xi);
        CVT(xi, ah, al, TOK, DI, DI, DI, 0);
        CVT(bcwl, wh, wl, BCDW, DI, DI, DI, 0);
        gemm_mma<<<dim3(TOK / 128, 1), 256, SMB>>>(ah, al, wh, wl, bcd,
                BCDW, DI, BCDW, 0);
        CVT(bcd, ah, al, TOK, DR, 64, BCDW, 2 * NSTATE);
        CVT(dwl, wh, wl, DI, DR, 64, DR, 0);
        gemm_mma<<<dim3(TOK / 128, DI / 128), 256, SMB>>>(ah, al, wh, wl, delta,
                DI, 64, DI, 0);
        softplus_k<<<EW, 256>>>(delta, dbl);
        scan_k<<<BB * (DI / 8), 128>>>(lAl, Dpl, bcd, delta, xi, xz, y);
        CVT(y, ah, al, TOK, DI, DI, DI, 0);
        CVT(owl, wh, wl, D, DI, DI, DI, 0);
        gemm_mma<<<dim3(TOK / 128, D / 128), 256, SMB>>>(ah, al, wh, wl, h,
                D, DI, D, 1);               // accum=1: fused residual
    }

    rmsnorm_k<<<TOK, 256>>>(h, norm_f_w, hn);
    CVT(hn, ah, al, TOK, D, D, D, 0);
    gemm_mma<<<dim3(TOK / 128, VOC / 128), 256, SMB>>>(ah, al, eh, el, out,
            VOC, D, VOC, 0);
}